// round 8
// baseline (speedup 1.0000x reference)
#include <cuda_runtime.h>
#include <math.h>
#include <stdint.h>

// ----------------------------------------------------------------------------
// LiteTracker correlation-pyramid hot path.
//   corr (fp32, per level): bilinear patch gather + 49x49x128 per-point GEMM
//        -> g_x[l] [4096 x 2432]  (2401 real cols + zeroed pad)
//   GEMM1 (tf32 tensor cores): [16384 x 2432pad] @ w1[2401 x 384] + b1, GELU
//        -> g_h [16384 x 384]
//   GEMM2 (fp32): [16384 x 384] @ w2[384 x 256] + b2 -> out[n, level*256 + j]
// Inputs resolved BY ELEMENT COUNT (ordering-agnostic).
// ----------------------------------------------------------------------------

#define NPTS   4096
#define CCH    128
#define GSZ    7
#define GG     49
#define XDIM   2401
#define XPAD   2432      // 76 * 32, float4-aligned rows, no K-tail in GEMM1
#define HID1   384
#define HID2   256
#define NLEV   4

// scratch (device globals; no allocations allowed)
__device__ float g_x[(size_t)NLEV * NPTS * XPAD];   // ~159 MB
__device__ float g_h[(size_t)NLEV * NPTS * HID1];   // ~25 MB

// ---------------------------- corr kernel -----------------------------------
#define ST_STRIDE 52
#define P_STRIDE  65
#define SMEM_ST_FLOATS (CCH * ST_STRIDE)
#define SMEM_PT_FLOATS (CCH * P_STRIDE)
#define CORR_SMEM_BYTES ((SMEM_ST_FLOATS + SMEM_PT_FLOATS) * 4)

__global__ __launch_bounds__(256) void corr_kernel(
    const float* __restrict__ fmap,    // [128][H][W]
    const float* __restrict__ tfeat,   // [49][4096][128]
    const float* __restrict__ coords,  // [4096][2]
    int level, int H, int W, float scale)
{
  extern __shared__ float sm[];
  float* St = sm;                       // stride ST_STRIDE
  float* PT = sm + SMEM_ST_FLOATS;      // patch (stride 65) then Tt (stride 52)

  const int n   = blockIdx.x;
  const int tid = threadIdx.x;

  const float x  = coords[2 * n + 0] * scale;
  const float y  = coords[2 * n + 1] * scale;
  const float fx = floorf(x), fy = floorf(y);
  const float wx = x - fx,    wy = y - fy;
  const int ix0 = (int)fx - 3;
  const int iy0 = (int)fy - 3;
  const int HW  = H * W;

  // phase 1: load 8x8 pixel patch for all 128 channels (zero outside image).
  for (int idx = tid; idx < CCH * 64; idx += 256) {
    const int c = idx >> 6, p = idx & 63;
    const int yy = p >> 3, xx = p & 7;
    const int gy = iy0 + yy, gx2 = ix0 + xx;
    float v = 0.f;
    if (gy >= 0 && gy < H && gx2 >= 0 && gx2 < W)
      v = fmap[c * HW + gy * W + gx2];
    PT[c * P_STRIDE + p] = v;
  }
  for (int idx = tid; idx < CCH * (ST_STRIDE - GG); idx += 256) {
    const int c = idx / (ST_STRIDE - GG), k = idx % (ST_STRIDE - GG);
    St[c * ST_STRIDE + GG + k] = 0.f;
  }
  __syncthreads();

  // phase 2: bilinear combine into St[c][hw].
  const float omx = 1.f - wx, omy = 1.f - wy;
  for (int idx = tid; idx < GG * CCH; idx += 256) {
    const int hw = idx >> 7, c = idx & 127;
    const int h = hw / GSZ, w = hw - h * GSZ;
    const float* Pr = &PT[c * P_STRIDE];
    const float v00 = Pr[w * 8 + h];
    const float v01 = Pr[w * 8 + h + 1];         // x+1
    const float v10 = Pr[(w + 1) * 8 + h];       // y+1
    const float v11 = Pr[(w + 1) * 8 + h + 1];
    St[c * ST_STRIDE + hw] =
        omy * (omx * v00 + wx * v01) + wy * (omx * v10 + wx * v11);
  }
  __syncthreads();

  // phase 3: load template feats Tt[c][ij] (reuses patch smem region)
  const float* tf = tfeat + (size_t)n * CCH;
  for (int idx = tid; idx < GG * CCH; idx += 256) {
    const int ij = idx >> 7, c = idx & 127;
    PT[c * ST_STRIDE + ij] = tf[(size_t)ij * ((size_t)NPTS * CCH) + c];
  }
  for (int idx = tid; idx < CCH * (ST_STRIDE - GG); idx += 256) {
    const int c = idx / (ST_STRIDE - GG), k = idx % (ST_STRIDE - GG);
    PT[c * ST_STRIDE + GG + k] = 0.f;
  }
  __syncthreads();

  // phase 4: 49x49 correlation, 4x4 register tiles on a 13x13 active grid
  float* xrow = &g_x[((size_t)level * NPTS + n) * XPAD];
  const int ty = tid >> 4, tx = tid & 15;
  const int r0 = ty * 4, c0 = tx * 4;
  if (r0 < GG && c0 < GG) {
    float acc[4][4] = {};
    #pragma unroll 4
    for (int c = 0; c < CCH; ++c) {
      const float4 sv = *(const float4*)&St[c * ST_STRIDE + r0];
      const float4 tv = *(const float4*)&PT[c * ST_STRIDE + c0];
      const float s[4] = {sv.x, sv.y, sv.z, sv.w};
      const float t[4] = {tv.x, tv.y, tv.z, tv.w};
      #pragma unroll
      for (int i = 0; i < 4; ++i)
        #pragma unroll
        for (int j = 0; j < 4; ++j)
          acc[i][j] = fmaf(s[i], t[j], acc[i][j]);
    }
    #pragma unroll
    for (int i = 0; i < 4; ++i) {
      const int r = r0 + i;
      if (r < GG) {
        #pragma unroll
        for (int j = 0; j < 4; ++j) {
          const int cc = c0 + j;
          if (cc < GG) xrow[r * GG + cc] = acc[i][j];
        }
      }
    }
  }
  // zero the pad cols 2401..2431 (so tf32 GEMM pad products are exactly 0)
  if (tid < XPAD - XDIM) xrow[XDIM + tid] = 0.f;
}

// ---------------------- GEMM1 (tf32 mma) + GELU -----------------------------
// [16384 x 2432pad] @ w1[2401 x 384] -> g_h.  Block 128x128x32, 8 warps,
// warp tile 32x64, mma.m16n8k8 tf32. Smem pads: A stride 36, B stride 136
// (both fragment LDS patterns bank-conflict-free).
#define G1_ASTR 36
#define G1_BSTR 136
#define G1_ASF  (128 * G1_ASTR)          // 4608 floats per stage
#define G1_BSF  (32 * G1_BSTR)           // 4352 floats per stage
#define G1_SMEM_BYTES ((2 * (G1_ASF + G1_BSF)) * 4)   // 71680 B
#define G1_KT  (XPAD / 32)               // 76 exact k-tiles

__device__ __forceinline__ float f2tf32(float f) {
  unsigned r;
  asm("cvt.rna.tf32.f32 %0, %1;" : "=r"(r) : "f"(f));
  return __uint_as_float(r);
}

__device__ __forceinline__ void mma_tf32(
    float& c0, float& c1, float& c2, float& c3,
    unsigned a0, unsigned a1, unsigned a2, unsigned a3,
    unsigned b0, unsigned b1)
{
  asm volatile(
      "mma.sync.aligned.m16n8k8.row.col.f32.tf32.tf32.f32 "
      "{%0,%1,%2,%3}, {%4,%5,%6,%7}, {%8,%9}, {%10,%11,%12,%13};"
      : "=f"(c0), "=f"(c1), "=f"(c2), "=f"(c3)
      : "r"(a0), "r"(a1), "r"(a2), "r"(a3), "r"(b0), "r"(b1),
        "f"(c0), "f"(c1), "f"(c2), "f"(c3));
}

__global__ __launch_bounds__(256) void gemm1_tc_kernel(
    const float* __restrict__ w1, const float* __restrict__ b1)
{
  extern __shared__ float sm1[];
  float* Asm[2] = { sm1, sm1 + G1_ASF };
  float* Bsm[2] = { sm1 + 2 * G1_ASF, sm1 + 2 * G1_ASF + G1_BSF };

  const int tid  = threadIdx.x;
  const int bm   = blockIdx.x * 128;
  const int bn   = blockIdx.y * 128;
  const int lane = tid & 31;
  const int warp = tid >> 5;
  const int wm   = warp >> 1;          // 0..3  (M)
  const int wn   = warp & 1;           // 0..1  (N)
  const int g    = lane >> 2;          // groupID 0..7
  const int tg   = lane & 3;           // thread-in-group 0..3

  float acc[2][8][4] = {};             // [mfrag][nfrag][c0..c3]
  float4 pa[4], pb[4];

  // --- global fetch of tile t into registers ---
  auto fetch = [&](int t) {
    const int k0 = t * 32;
    #pragma unroll
    for (int i = 0; i < 4; ++i) {
      const int idx = tid + i * 256;
      const int row = idx >> 3, f4 = (idx & 7) * 4;
      pa[i] = *(const float4*)&g_x[(size_t)(bm + row) * XPAD + k0 + f4];
      const int kr = idx >> 5, c4 = (idx & 31) * 4;
      const int kk = k0 + kr;
      pb[i] = (kk < XDIM)
          ? *(const float4*)&w1[(size_t)kk * HID1 + bn + c4]
          : make_float4(0.f, 0.f, 0.f, 0.f);
    }
  };
  // --- store registers into smem stage s (tf32-rounded) ---
  auto stage = [&](int s) {
    float* Ad = Asm[s];
    float* Bd = Bsm[s];
    #pragma unroll
    for (int i = 0; i < 4; ++i) {
      const int idx = tid + i * 256;
      const int row = idx >> 3, f4 = (idx & 7) * 4;
      float* d = Ad + row * G1_ASTR + f4;
      d[0] = f2tf32(pa[i].x); d[1] = f2tf32(pa[i].y);
      d[2] = f2tf32(pa[i].z); d[3] = f2tf32(pa[i].w);
      const int kr = idx >> 5, c4 = (idx & 31) * 4;
      float* e = Bd + kr * G1_BSTR + c4;
      e[0] = f2tf32(pb[i].x); e[1] = f2tf32(pb[i].y);
      e[2] = f2tf32(pb[i].z); e[3] = f2tf32(pb[i].w);
    }
  };

  fetch(0);
  stage(0);
  __syncthreads();

  const int aoff = (wm * 32 + g) * G1_ASTR + tg;   // + f*16*G1_ASTR, +8*G1_ASTR, +4, +kb
  const int boff = tg * G1_BSTR + wn * 64 + g;     // + j*8, +4*G1_BSTR, +kb*G1_BSTR

  for (int t = 0; t < G1_KT; ++t) {
    const int cur = t & 1;
    const bool hn = (t + 1 < G1_KT);
    if (hn) fetch(t + 1);

    const unsigned* Au = (const unsigned*)Asm[cur];
    const unsigned* Bu = (const unsigned*)Bsm[cur];
    #pragma unroll
    for (int ks = 0; ks < 4; ++ks) {
      const int kb = ks * 8;
      unsigned a[2][4], b[8][2];
      #pragma unroll
      for (int f = 0; f < 2; ++f) {
        const int base = aoff + f * 16 * G1_ASTR + kb;
        a[f][0] = Au[base];
        a[f][1] = Au[base + 8 * G1_ASTR];
        a[f][2] = Au[base + 4];
        a[f][3] = Au[base + 8 * G1_ASTR + 4];
      }
      const int bbase = boff + kb * G1_BSTR;
      #pragma unroll
      for (int j = 0; j < 8; ++j) {
        b[j][0] = Bu[bbase + j * 8];
        b[j][1] = Bu[bbase + j * 8 + 4 * G1_BSTR];
      }
      #pragma unroll
      for (int f = 0; f < 2; ++f)
        #pragma unroll
        for (int j = 0; j < 8; ++j)
          mma_tf32(acc[f][j][0], acc[f][j][1], acc[f][j][2], acc[f][j][3],
                   a[f][0], a[f][1], a[f][2], a[f][3], b[j][0], b[j][1]);
    }

    if (hn) {
      __syncthreads();
      stage(cur ^ 1);
      __syncthreads();
    }
  }

  // epilogue: bias + exact GELU, write g_h [16384][384]
  #pragma unroll
  for (int f = 0; f < 2; ++f) {
    const int m0 = bm + wm * 32 + f * 16 + g;
    #pragma unroll
    for (int j = 0; j < 8; ++j) {
      const int col = bn + wn * 64 + j * 8 + 2 * tg;
      const float bi0 = b1[col], bi1 = b1[col + 1];
      float v0 = acc[f][j][0] + bi0;
      float v1 = acc[f][j][1] + bi1;
      float v2 = acc[f][j][2] + bi0;
      float v3 = acc[f][j][3] + bi1;
      v0 = 0.5f * v0 * (1.f + erff(v0 * 0.70710678118654752f));
      v1 = 0.5f * v1 * (1.f + erff(v1 * 0.70710678118654752f));
      v2 = 0.5f * v2 * (1.f + erff(v2 * 0.70710678118654752f));
      v3 = 0.5f * v3 * (1.f + erff(v3 * 0.70710678118654752f));
      *(float2*)&g_h[(size_t)m0 * HID1 + col] = make_float2(v0, v1);
      *(float2*)&g_h[(size_t)(m0 + 8) * HID1 + col] = make_float2(v2, v3);
    }
  }
}

// ------------------------------- GEMM2 (fp32) -------------------------------
#define G2_BM 128
#define G2_BN 64
#define G2_BK 16
#define G2_AST 132

__global__ __launch_bounds__(256) void gemm2_kernel(
    const float* __restrict__ w2, const float* __restrict__ b2,
    float* __restrict__ out)
{
  __shared__ __align__(16) float As[2][G2_BK][G2_AST];
  __shared__ __align__(16) float Bs[2][G2_BK][G2_BN];

  const int K  = HID1;  // 384
  const int NN = HID2;  // 256
  const int tid = threadIdx.x;
  const int bm = blockIdx.x * G2_BM;
  const int bn = blockIdx.y * G2_BN;
  const float* A = g_h;

  const int ty = tid >> 4, tx = tid & 15;
  const int la_r = tid >> 2;        // rows la_r, la_r+64
  const int la_q = (tid & 3) * 4;   // k offset (float4)
  const int lb_k = tid >> 4;
  const int lb_c = (tid & 15) * 4;

  float acc[8][4] = {};

  { // tile 0
    #pragma unroll
    for (int s = 0; s < 2; ++s) {
      const int r = la_r + 64 * s;
      const float4 av = *(const float4*)&A[(size_t)(bm + r) * K + la_q];
      As[0][la_q + 0][r] = av.x; As[0][la_q + 1][r] = av.y;
      As[0][la_q + 2][r] = av.z; As[0][la_q + 3][r] = av.w;
    }
    *(float4*)&Bs[0][lb_k][lb_c] =
        *(const float4*)&w2[(size_t)lb_k * NN + bn + lb_c];
  }
  __syncthreads();

  const int KT = K / G2_BK;  // 24
  for (int t = 0; t < KT; ++t) {
    const int cur = t & 1;
    float4 pa[2], pb;
    const bool hn = (t + 1 < KT);
    if (hn) {
      const int k0 = (t + 1) * G2_BK;
      #pragma unroll
      for (int s = 0; s < 2; ++s)
        pa[s] = *(const float4*)&A[(size_t)(bm + la_r + 64 * s) * K + k0 + la_q];
      pb = *(const float4*)&w2[(size_t)(k0 + lb_k) * NN + bn + lb_c];
    }
    #pragma unroll
    for (int k = 0; k < G2_BK; ++k) {
      float a[8], b[4];
      *(float4*)&a[0] = *(const float4*)&As[cur][k][ty * 8];
      *(float4*)&a[4] = *(const float4*)&As[cur][k][ty * 8 + 4];
      *(float4*)&b[0] = *(const float4*)&Bs[cur][k][tx * 4];
      #pragma unroll
      for (int i = 0; i < 8; ++i)
        #pragma unroll
        for (int j = 0; j < 4; ++j)
          acc[i][j] = fmaf(a[i], b[j], acc[i][j]);
    }
    if (hn) {
      __syncthreads();
      const int nxt = cur ^ 1;
      #pragma unroll
      for (int s = 0; s < 2; ++s) {
        const int r = la_r + 64 * s;
        As[nxt][la_q + 0][r] = pa[s].x; As[nxt][la_q + 1][r] = pa[s].y;
        As[nxt][la_q + 2][r] = pa[s].z; As[nxt][la_q + 3][r] = pa[s].w;
      }
      *(float4*)&Bs[nxt][lb_k][lb_c] = pb;
      __syncthreads();
    }
  }

  float bb[4];
  #pragma unroll
  for (int j = 0; j < 4; ++j) bb[j] = b2[bn + tx * 4 + j];
  #pragma unroll
  for (int i = 0; i < 8; ++i) {
    const int m   = bm + ty * 8 + i;
    const int n   = m & (NPTS - 1);
    const int lvl = m >> 12;
    float v[4];
    #pragma unroll
    for (int j = 0; j < 4; ++j) v[j] = acc[i][j] + bb[j];
    *(float4*)&out[(size_t)n * (NLEV * HID2) + lvl * HID2 + bn + tx * 4] =
        *(float4*)&v[0];
  }
}

// ------------------------------- launch -------------------------------------
// Resolve inputs purely by element count (ordering-agnostic):
//   tfeat*  : 25690112 (x4, order of appearance = level 0..3)
//   fmaps0  : 1572864, fmaps1: 393216, fmaps3: 24576  (unique)
//   98304   : first occurrence = fmaps2, second = w2
//   coords  : 8192, w1: 921984, b1: 384, b2: 256
extern "C" void kernel_launch(void* const* d_in, const int* in_sizes, int n_in,
                              void* d_out, int out_size)
{
  const float *fm[4] = {0,0,0,0}, *tf[4] = {0,0,0,0};
  const float *coords = 0, *w1 = 0, *b1 = 0, *w2 = 0, *b2 = 0;
  int ntf = 0, n98k = 0;

  for (int i = 0; i < n_in; ++i) {
    const float* p = (const float*)d_in[i];
    switch (in_sizes[i]) {
      case 25690112: if (ntf < 4) tf[ntf++] = p; break;
      case 1572864:  fm[0] = p; break;
      case 393216:   fm[1] = p; break;
      case 98304:    if (n98k++ == 0) fm[2] = p; else w2 = p; break;
      case 24576:    fm[3] = p; break;
      case 8192:     coords = p; break;
      case 921984:   w1 = p; break;
      case 384:      b1 = p; break;
      case 256:      b2 = p; break;
      default: break;
    }
  }

  static const int Hs[4] = {96, 48, 24, 12};
  static const int Ws[4] = {128, 64, 32, 16};

  cudaFuncSetAttribute(corr_kernel, cudaFuncAttributeMaxDynamicSharedMemorySize,
                       CORR_SMEM_BYTES);
  cudaFuncSetAttribute(gemm1_tc_kernel,
                       cudaFuncAttributeMaxDynamicSharedMemorySize,
                       G1_SMEM_BYTES);

  for (int l = 0; l < 4; ++l) {
    const float scale = 1.f / (float)(1 << l);
    corr_kernel<<<NPTS, 256, CORR_SMEM_BYTES>>>(fm[l], tf[l], coords, l,
                                                Hs[l], Ws[l], scale);
  }
  gemm1_tc_kernel<<<dim3(16384 / 128, HID1 / 128), 256, G1_SMEM_BYTES>>>(w1, b1);
  gemm2_kernel<<<dim3(16384 / G2_BM, HID2 / G2_BN), 256>>>(w2, b2,
                                                           (float*)d_out);
}